// round 5
// baseline (speedup 1.0000x reference)
#include <cuda_runtime.h>
#include <cuda_bf16.h>

// y[b,c,h,w] = coef[c] * g[b,c,h,w]
// g: (32, 512, 64, 64) fp32, coef: (512,) fp32.
//
// One block = 256 threads x 8 float4 = 8192 floats = exactly TWO consecutive
// (b,c) channel planes. Grid = 32*512/2 = 8192 blocks.
//   plane0 channel: c0 = (2*blockIdx.x)   & 511   -> scale s0
//   plane1 channel: c1 = (2*blockIdx.x+1) & 511   -> scale s1
// Both block-uniform (uniform-register path, zero per-element index math).
//
// ILP=8: 8 front-batched LDG.128.EF per thread (MLP=8 outstanding DRAM
// requests/thread), then FMULs, then 8 STG.128.EF.
// .EF (evict-first) streaming policy: zero-reuse 512 MiB stream -> minimize
// L2 write-allocate thrash against read fills.

__global__ __launch_bounds__(256)
void Gradient_28733331210651_kernel(const float4* __restrict__ g4,
                                    const float* __restrict__ coef,
                                    float4* __restrict__ out4) {
    const int c0 = (blockIdx.x << 1) & 511;
    const float s0 = __ldg(coef + c0);
    const float s1 = __ldg(coef + c0 + 1);

    const long long base = (long long)blockIdx.x * 2048 + threadIdx.x;

    // Front-batched loads (MLP=8)
    float4 v0 = __ldcs(g4 + base);
    float4 v1 = __ldcs(g4 + base + 256);
    float4 v2 = __ldcs(g4 + base + 512);
    float4 v3 = __ldcs(g4 + base + 768);
    float4 v4 = __ldcs(g4 + base + 1024);
    float4 v5 = __ldcs(g4 + base + 1280);
    float4 v6 = __ldcs(g4 + base + 1536);
    float4 v7 = __ldcs(g4 + base + 1792);

    // First 4 groups lie in plane c0, last 4 in plane c0+1
    v0.x *= s0; v0.y *= s0; v0.z *= s0; v0.w *= s0;
    v1.x *= s0; v1.y *= s0; v1.z *= s0; v1.w *= s0;
    v2.x *= s0; v2.y *= s0; v2.z *= s0; v2.w *= s0;
    v3.x *= s0; v3.y *= s0; v3.z *= s0; v3.w *= s0;
    v4.x *= s1; v4.y *= s1; v4.z *= s1; v4.w *= s1;
    v5.x *= s1; v5.y *= s1; v5.z *= s1; v5.w *= s1;
    v6.x *= s1; v6.y *= s1; v6.z *= s1; v6.w *= s1;
    v7.x *= s1; v7.y *= s1; v7.z *= s1; v7.w *= s1;

    __stcs(out4 + base,        v0);
    __stcs(out4 + base + 256,  v1);
    __stcs(out4 + base + 512,  v2);
    __stcs(out4 + base + 768,  v3);
    __stcs(out4 + base + 1024, v4);
    __stcs(out4 + base + 1280, v5);
    __stcs(out4 + base + 1536, v6);
    __stcs(out4 + base + 1792, v7);
}

extern "C" void kernel_launch(void* const* d_in, const int* in_sizes, int n_in,
                              void* d_out, int out_size) {
    const float4* g4   = (const float4*)d_in[0];
    const float*  coef = (const float*)d_in[1];
    float4*       out4 = (float4*)d_out;

    // 32*512*64*64 floats; one block per 8192-float pair of channel planes
    long long n  = (long long)in_sizes[0];      // 67108864
    long long blocks = n >> 13;                 // 8192

    Gradient_28733331210651_kernel<<<(unsigned)blocks, 256>>>(g4, coef, out4);
}

// round 7
// speedup vs baseline: 1.0043x; 1.0043x over previous
#include <cuda_runtime.h>
#include <cuda_bf16.h>

// y[b,c,h,w] = coef[c] * g[b,c,h,w]
// g: (32, 512, 64, 64) fp32, coef: (512,) fp32.
//
// One block = one (b,c) channel plane (4096 floats = 16 KiB). Grid = 16384.
// coef index is block-uniform: c = blockIdx.x & 511.
//
// 256-bit global accesses (sm_100+): each thread does 2x LDG.E.256 (32 B each)
// and 2x STG.E.256. Same bytes/thread as the best MLP=4x128-bit config (R4:
// 73.3us, DRAM 83%), but half the LSU instructions and L1tex wavefront-queue
// entries. .cs streaming policy: zero-reuse 512 MiB stream, evict-first.
//
// Thread t covers floats [t*8, t*8+8) and [2048 + t*8, 2048 + t*8 + 8) of the
// plane: 256 threads x 16 floats = 4096. All accesses 32 B aligned.

__global__ __launch_bounds__(256)
void Gradient_28733331210651_kernel(const float* __restrict__ g,
                                    const float* __restrict__ coef,
                                    float* __restrict__ out) {
    const int c = blockIdx.x & 511;
    const float s = __ldg(coef + c);

    const long long plane = (long long)blockIdx.x * 4096;
    const float* p0 = g + plane + threadIdx.x * 8;
    const float* p1 = p0 + 2048;
    float* q0 = out + plane + threadIdx.x * 8;
    float* q1 = q0 + 2048;

    unsigned a0, a1, a2, a3, a4, a5, a6, a7;
    unsigned b0, b1, b2, b3, b4, b5, b6, b7;

    // Front-batched 256-bit streaming loads
    asm volatile("ld.global.cs.v8.b32 {%0,%1,%2,%3,%4,%5,%6,%7}, [%8];"
                 : "=r"(a0), "=r"(a1), "=r"(a2), "=r"(a3),
                   "=r"(a4), "=r"(a5), "=r"(a6), "=r"(a7)
                 : "l"(p0));
    asm volatile("ld.global.cs.v8.b32 {%0,%1,%2,%3,%4,%5,%6,%7}, [%8];"
                 : "=r"(b0), "=r"(b1), "=r"(b2), "=r"(b3),
                   "=r"(b4), "=r"(b5), "=r"(b6), "=r"(b7)
                 : "l"(p1));

    a0 = __float_as_uint(__uint_as_float(a0) * s);
    a1 = __float_as_uint(__uint_as_float(a1) * s);
    a2 = __float_as_uint(__uint_as_float(a2) * s);
    a3 = __float_as_uint(__uint_as_float(a3) * s);
    a4 = __float_as_uint(__uint_as_float(a4) * s);
    a5 = __float_as_uint(__uint_as_float(a5) * s);
    a6 = __float_as_uint(__uint_as_float(a6) * s);
    a7 = __float_as_uint(__uint_as_float(a7) * s);
    b0 = __float_as_uint(__uint_as_float(b0) * s);
    b1 = __float_as_uint(__uint_as_float(b1) * s);
    b2 = __float_as_uint(__uint_as_float(b2) * s);
    b3 = __float_as_uint(__uint_as_float(b3) * s);
    b4 = __float_as_uint(__uint_as_float(b4) * s);
    b5 = __float_as_uint(__uint_as_float(b5) * s);
    b6 = __float_as_uint(__uint_as_float(b6) * s);
    b7 = __float_as_uint(__uint_as_float(b7) * s);

    asm volatile("st.global.cs.v8.b32 [%0], {%1,%2,%3,%4,%5,%6,%7,%8};"
                 :: "l"(q0),
                    "r"(a0), "r"(a1), "r"(a2), "r"(a3),
                    "r"(a4), "r"(a5), "r"(a6), "r"(a7)
                 : "memory");
    asm volatile("st.global.cs.v8.b32 [%0], {%1,%2,%3,%4,%5,%6,%7,%8};"
                 :: "l"(q1),
                    "r"(b0), "r"(b1), "r"(b2), "r"(b3),
                    "r"(b4), "r"(b5), "r"(b6), "r"(b7)
                 : "memory");
}

extern "C" void kernel_launch(void* const* d_in, const int* in_sizes, int n_in,
                              void* d_out, int out_size) {
    const float* g    = (const float*)d_in[0];
    const float* coef = (const float*)d_in[1];
    float*       out  = (float*)d_out;

    // 32*512*64*64 floats; one block per 4096-float channel plane
    long long n  = (long long)in_sizes[0];      // 67108864
    long long blocks = n >> 12;                 // 16384

    Gradient_28733331210651_kernel<<<(unsigned)blocks, 256>>>(g, coef, out);
}